// round 14
// baseline (speedup 1.0000x reference)
#include <cuda_runtime.h>

#define HID  128
#define MH   64
#define D32  32
#define OUTD 128
#define NB   128   // grid; 8 rows per block; <= SM count (co-resident)

// ---- device globals (no allocation allowed) ----
__device__ float        g_part[NB * 128]; // [b][0:64)=hid, [64:96)=a, [96:128)=c
__device__ float        g_final[192];     // [0:32)=S, [32:64)=T, [64:192)=K
__device__ int          g_cnt;            // phase-A ticket (reducer resets)
__device__ int          g_cnt2;           // post-spin ticket (last resets flags)
__device__ volatile int g_flag1;          // reducer -> consumers: S/T ready
__device__ volatile int g_flag2;          // reducer -> consumers: K ready

__global__ void __launch_bounds__(512) kf(
    const float* __restrict__ hs,
    const float* __restrict__ obs1,
    const float* __restrict__ obs,
    const float* __restrict__ W_sp,
    const float* __restrict__ b_sp,
    const float* __restrict__ W_vel,
    const float* __restrict__ b_vel,
    const float* __restrict__ W_hid,
    const float* __restrict__ b_hid,
    const float* __restrict__ W_out,
    const float* __restrict__ b_out,
    float* __restrict__ out)
{
    __shared__ float wS[HID][MH];   // 32 KB; tail + phase-C scratch alias here
    __shared__ float hsS[8][HID];   // 4 KB
    __shared__ float bhS[MH];
    __shared__ float sa[8][D32];    // 1 KB  (kept live for phase C)
    __shared__ float sc[8][D32];    // 1 KB  (kept live for phase C)
    __shared__ float p0[8][MH];     // 2 KB
    __shared__ float p1[8][MH];     // 2 KB
    __shared__ float red[4][MH];    // 1 KB
    __shared__ int   isLast;

    int b = blockIdx.x, t = threadIdx.x;
    int row0 = b * 8;

    // phase-C GEMM role: o(128) x ch(2 d-halves) x rh(2 row-quads)
    int o = t & 127, g4 = t >> 7;
    int ch = g4 & 1, rh = g4 >> 1;

    // ========== phase A staging: ALL loads independent, one wave ==========
    float w[32];                    // this thread's W_out[ch*32 + j][o] values
    {
        const float* wp = W_out + ch * 32 * OUTD + o;
        #pragma unroll
        for (int j = 0; j < 32; j++) w[j] = __ldg(&wp[j * OUTD]);
    }

    #pragma unroll
    for (int j = 0; j < 4; j++)     // W_hid: 2048 float4
        ((float4*)wS)[t + 512 * j] = ((const float4*)W_hid)[t + 512 * j];

    if (t < 64) bhS[t] = b_hid[t];

    if (t < 256) {
        ((float4*)hsS)[t] = ((const float4*)(hs + row0 * HID))[t];
    } else {
        int tt = t - 256;
        int row = tt >> 5, d = tt & 31;
        int i = row0 + row;
        float2 oo = ((const float2*)obs)[i];
        float2 o1 = ((const float2*)obs1)[i];
        sa[row][d] = fmaf(oo.x, W_sp[d], oo.y * W_sp[D32 + d]);
        float vx = 4.f * (oo.x - o1.x), vy = 4.f * (oo.y - o1.y);
        sc[row][d] = fmaf(vx, W_vel[d], vy * W_vel[D32 + d]);
    }
    __syncthreads();

    {   // hidden GEMM from smem: k(64) x ch2(2 c-halves) x rg(4 row-pairs)
        int k = t & 63, g = t >> 6;
        int ch2 = g & 1, rg = g >> 1;
        const float* wp = &wS[ch2 * 64][k];
        const float* h0 = &hsS[rg * 2][ch2 * 64];
        const float* h1 = &hsS[rg * 2 + 1][ch2 * 64];
        float a0 = 0.f, a1 = 0.f;
        #pragma unroll
        for (int c = 0; c < 64; c++) {
            float ww = wp[c * MH];
            a0 = fmaf(h0[c], ww, a0);
            a1 = fmaf(h1[c], ww, a1);
        }
        p0[g][k] = a0;
        p1[g][k] = a1;
    }
    __syncthreads();

    if (t < 256) {
        int k = t & 63, rg = t >> 6;
        float bk = bhS[k];
        float a0 = bk + p0[rg * 2][k] + p0[rg * 2 + 1][k];
        float a1 = bk + p1[rg * 2][k] + p1[rg * 2 + 1][k];
        red[rg][k] = fmaxf(fmaxf(a0, a1), 0.f);
    }
    __syncthreads();

    if (t < 64) {
        g_part[b * 128 + t] = fmaxf(fmaxf(red[0][t], red[1][t]),
                                    fmaxf(red[2][t], red[3][t]));
    } else if (t < 96) {
        int d = t - 64;
        float m = sa[0][d];
        #pragma unroll
        for (int r = 1; r < 8; r++) m = fmaxf(m, sa[r][d]);
        g_part[b * 128 + t] = m;
    } else if (t < 128) {
        int d = t - 96;
        float m = sc[0][d];
        #pragma unroll
        for (int r = 1; r < 8; r++) m = fmaxf(m, sc[r][d]);
        g_part[b * 128 + t] = m;
    }
    __threadfence();
    if (t == 0) isLast = (atomicAdd(&g_cnt, 1) == NB - 1);
    __syncthreads();

    // ========== reducer tail (last-arriving block only) ==========
    if (isLast) {
        float* red2  = &wS[0][0];    // [4][128] — aliases wS (done with weights)
        float* hmS   = red2 + 512;   // [64]
        float* biasS = hmS + 64;     // [192]
        float* kred  = biasS + 192;  // [4][128]

        if (t < 192)
            biasS[t] = (t < 32) ? b_sp[t]
                     : (t < 64) ? b_vel[t - 32] : b_out[t - 64];

        {   // reduce 128 partials: 128 cols x 4 groups x 32 rows (independent)
            int col = t & 127, grp = t >> 7;
            const float* p = g_part + grp * 32 * 128 + col;
            float m = -3.4e38f;
            #pragma unroll
            for (int q = 0; q < 32; q++) m = fmaxf(m, __ldcg(&p[q * 128]));
            red2[grp * 128 + col] = m;
        }
        __syncthreads();
        if (t < 128) {
            float v = fmaxf(fmaxf(red2[t], red2[128 + t]),
                            fmaxf(red2[256 + t], red2[384 + t]));
            if (t < 64) hmS[t] = v;
            else        g_final[t - 64] = v + biasS[t - 64];   // S then T
        }
        __syncthreads();
        __threadfence();
        if (t == 0) g_flag1 = 1;     // S/T ready — consumers may start

        {   // K[o] = b_out[o] + sum_k hm[k]*W_out[64+k][o]  (overlaps consumers)
            int oo = t & 127, kh = t >> 7;
            float acc = 0.f;
            #pragma unroll
            for (int j = 0; j < 16; j++) {
                int k = kh * 16 + j;
                acc = fmaf(hmS[k], __ldg(&W_out[(64 + k) * OUTD + oo]), acc);
            }
            kred[kh * 128 + oo] = acc;
        }
        __syncthreads();
        if (t < 128)
            g_final[64 + t] = biasS[64 + t] + kred[t] + kred[128 + t]
                                            + kred[256 + t] + kred[384 + t];
        if (t == 0) g_cnt = 0;       // reset phase-A ticket (reducer is last)
        __threadfence();
        if (t == 0) g_flag2 = 1;     // K ready
    }

    // ========== spin #1: wait for S/T ==========
    if (t == 0) {
        while (g_flag1 == 0) __nanosleep(100);
    }
    __syncthreads();

    // ========== phase C: features from live sa/sc, GEMM from registers ==========
    float* KS   = &wS[0][0] + 2048;  // [128] — clear of tail scratch [0,1280)
    float* fS   = KS + 128;          // [8][64] = 512 floats
    float* part = fS + 512;          // [4][4][128] = 2048 floats

    {   // feature: one slot per thread (8 rows x 64 d)
        int frow = t >> 6, fd = t & 63;
        float stv = __ldcg(&g_final[fd]);            // S[fd] or T[fd-32]
        float av  = (fd < D32) ? sa[frow][fd] : sc[frow][fd - D32];
        fS[frow * 64 + fd] = fmaxf(stv - av, 0.f);
    }
    __syncthreads();

    {   // GEMM: registers w[] x smem f  (overlaps reducer's K-fold)
        float acc[4] = {0.f, 0.f, 0.f, 0.f};
        #pragma unroll
        for (int j = 0; j < 32; j++) {
            #pragma unroll
            for (int r = 0; r < 4; r++)
                acc[r] = fmaf(fS[(rh * 4 + r) * 64 + ch * 32 + j], w[j], acc[r]);
        }
        #pragma unroll
        for (int r = 0; r < 4; r++)
            part[(g4 * 4 + r) * 128 + o] = acc[r];
    }

    // ========== spin #2: wait for K (usually already set) ==========
    if (t == 0) {
        while (g_flag2 == 0) __nanosleep(100);
        // past both spins: last block resets flags for the next graph replay
        if (atomicAdd(&g_cnt2, 1) == NB - 1) {
            g_flag1 = 0; g_flag2 = 0; g_cnt2 = 0;
        }
    }
    __syncthreads();

    if (t < 128) KS[t] = __ldcg(&g_final[64 + t]);
    __syncthreads();

    {   // combine d-halves + K, write out: 1024 outputs, 2 per thread
        #pragma unroll
        for (int s = 0; s < 2; s++) {
            int slot = t + 512 * s;
            int row = slot >> 7, oo2 = slot & 127;
            int rh2 = row >> 2, r = row & 3;
            out[(row0 + row) * OUTD + oo2] =
                KS[oo2] + part[((rh2 * 2) * 4 + r) * 128 + oo2]
                        + part[((rh2 * 2 + 1) * 4 + r) * 128 + oo2];
        }
    }
}

extern "C" void kernel_launch(void* const* d_in, const int* in_sizes, int n_in,
                              void* d_out, int out_size)
{
    const float* hs    = (const float*)d_in[0];
    const float* obs1  = (const float*)d_in[1];
    const float* obs   = (const float*)d_in[2];
    const float* W_sp  = (const float*)d_in[3];
    const float* b_sp  = (const float*)d_in[4];
    const float* W_vel = (const float*)d_in[5];
    const float* b_vel = (const float*)d_in[6];
    const float* W_hid = (const float*)d_in[7];
    const float* b_hid = (const float*)d_in[8];
    const float* W_out = (const float*)d_in[9];
    const float* b_out = (const float*)d_in[10];
    float* out = (float*)d_out;

    kf<<<NB, 512>>>(hs, obs1, obs, W_sp, b_sp, W_vel, b_vel,
                    W_hid, b_hid, W_out, b_out, out);
}

// round 15
// speedup vs baseline: 1.1120x; 1.1120x over previous
#include <cuda_runtime.h>

#define HID  128
#define MH   64
#define D32  32
#define OUTD 128
#define NB   128   // grid; 8 rows per block; <= SM count (co-resident)

// ---- device globals (no allocation allowed) ----
// 128 max-slots, each padded to its own 128B line (32 uints) to spread L2 slices.
// [0:64)=hid, [64:96)=a(spatial), [96:128)=c(vel). 0 = sentinel (< enc(any finite)).
__device__ unsigned     g_amax[128 * 32];
__device__ int          g_cnt;    // phase-A ticket (last setter resets)
__device__ int          g_cnt2;   // post-read ticket (last reader resets + zeroes)
__device__ volatile int g_flag;

// order-preserving float <-> uint encoding (unsigned compare == float compare)
__device__ __forceinline__ unsigned enc(float f) {
    unsigned u = __float_as_uint(f);
    return (u & 0x80000000u) ? ~u : (u | 0x80000000u);
}
__device__ __forceinline__ float dec(unsigned e) {
    return (e & 0x80000000u) ? __uint_as_float(e & 0x7FFFFFFFu)
                             : __uint_as_float(~e);
}

__global__ void __launch_bounds__(512) kf(
    const float* __restrict__ hs,
    const float* __restrict__ obs1,
    const float* __restrict__ obs,
    const float* __restrict__ W_sp,
    const float* __restrict__ b_sp,
    const float* __restrict__ W_vel,
    const float* __restrict__ b_vel,
    const float* __restrict__ W_hid,
    const float* __restrict__ b_hid,
    const float* __restrict__ W_out,
    const float* __restrict__ b_out,
    float* __restrict__ out)
{
    __shared__ float wS[HID][MH];   // 32 KB; phase-B/C scratch aliases here
    __shared__ float hsS[8][HID];   // 4 KB
    __shared__ float bhS[MH];       // 256 B
    __shared__ float biasS[192];    // 768 B: [0:32) b_sp, [32:64) b_vel, [64:192) b_out
    __shared__ float sa[8][D32];    // 1 KB (live into phase C)
    __shared__ float sc[8][D32];    // 1 KB (live into phase C)
    __shared__ float p0[8][MH];     // 2 KB
    __shared__ float p1[8][MH];     // 2 KB
    __shared__ float red[4][MH];    // 1 KB
    __shared__ int   isLast, lastRead;

    int b = blockIdx.x, t = threadIdx.x;
    int row0 = b * 8;

    // phase-C roles: o(128) x g4(4); ch = d-half, rh = row-quad
    int o = t & 127, g4 = t >> 7;
    int ch = g4 & 1, rh = g4 >> 1;

    // ========== phase A staging: ALL loads independent, one wave ==========
    float w[32];                    // W_out[ch*32 + j][o]   (phase-C GEMM)
    float w2[16];                   // W_out[64 + g4*16 + j][o]  (local K-fold)
    {
        const float* wp = W_out + ch * 32 * OUTD + o;
        #pragma unroll
        for (int j = 0; j < 32; j++) w[j] = __ldg(&wp[j * OUTD]);
        const float* wp2 = W_out + (64 + g4 * 16) * OUTD + o;
        #pragma unroll
        for (int j = 0; j < 16; j++) w2[j] = __ldg(&wp2[j * OUTD]);
    }

    #pragma unroll
    for (int j = 0; j < 4; j++)     // W_hid: 2048 float4
        ((float4*)wS)[t + 512 * j] = ((const float4*)W_hid)[t + 512 * j];

    if (t < 64) bhS[t] = b_hid[t];
    if (t >= 64 && t < 256) {       // biases (independent)
        int x = t - 64;
        if (x < 192)
            biasS[x] = (x < 32) ? b_sp[x] : (x < 64) ? b_vel[x - 32]
                                                     : b_out[x - 64];
    }

    if (t < 256) {
        ((float4*)hsS)[t] = ((const float4*)(hs + row0 * HID))[t];
    } else {
        int tt = t - 256;
        int row = tt >> 5, d = tt & 31;
        int i = row0 + row;
        float2 oo = ((const float2*)obs)[i];
        float2 o1 = ((const float2*)obs1)[i];
        sa[row][d] = fmaf(oo.x, W_sp[d], oo.y * W_sp[D32 + d]);
        float vx = 4.f * (oo.x - o1.x), vy = 4.f * (oo.y - o1.y);
        sc[row][d] = fmaf(vx, W_vel[d], vy * W_vel[D32 + d]);
    }
    __syncthreads();

    {   // hidden GEMM from smem: k(64) x ch2(2 c-halves) x rg(4 row-pairs)
        int k = t & 63, g = t >> 6;
        int ch2 = g & 1, rg = g >> 1;
        const float* wp = &wS[ch2 * 64][k];
        const float* h0 = &hsS[rg * 2][ch2 * 64];
        const float* h1 = &hsS[rg * 2 + 1][ch2 * 64];
        float a0 = 0.f, a1 = 0.f;
        #pragma unroll
        for (int c = 0; c < 64; c++) {
            float ww = wp[c * MH];
            a0 = fmaf(h0[c], ww, a0);
            a1 = fmaf(h1[c], ww, a1);
        }
        p0[g][k] = a0;
        p1[g][k] = a1;
    }
    __syncthreads();

    if (t < 256) {                  // combine c-halves, relu, max over 2 rows
        int k = t & 63, rg = t >> 6;
        float bk = bhS[k];
        float a0 = bk + p0[rg * 2][k] + p0[rg * 2 + 1][k];
        float a1 = bk + p1[rg * 2][k] + p1[rg * 2 + 1][k];
        red[rg][k] = fmaxf(fmaxf(a0, a1), 0.f);
    }
    __syncthreads();

    // per-block maxes -> padded global atomicMax slots (spread across L2 slices)
    if (t < 64) {
        float m = fmaxf(fmaxf(red[0][t], red[1][t]),
                        fmaxf(red[2][t], red[3][t]));
        atomicMax(&g_amax[t * 32], enc(m));
    } else if (t < 96) {
        int d = t - 64;
        float m = sa[0][d];
        #pragma unroll
        for (int r = 1; r < 8; r++) m = fmaxf(m, sa[r][d]);
        atomicMax(&g_amax[t * 32], enc(m));
    } else if (t < 128) {
        int d = t - 96;
        float m = sc[0][d];
        #pragma unroll
        for (int r = 1; r < 8; r++) m = fmaxf(m, sc[r][d]);
        atomicMax(&g_amax[t * 32], enc(m));
    }
    __syncthreads();                // all atomics issued before the ticket
    __threadfence();
    if (t == 0) {
        if (atomicAdd(&g_cnt, 1) == NB - 1) {
            g_cnt = 0;              // safe: provably last incrementer
            g_flag = 1;             // maxes are already final -> release
        }
        while (g_flag == 0) __nanosleep(100);
    }
    __syncthreads();

    // ========== phase B: read maxes (1 L2 wave), local K, features ==========
    float* hm = &wS[0][0];          // [64]   — aliases wS (weights done)
    float* ST = hm + 64;            // [64]: [0:32)=S, [32:64)=T
    float* fS = ST + 64;            // [8][64] = 512
    float* kp = fS + 512;           // [4][128] = 512
    float* part = kp + 512;         // [4][4][128] = 2048

    if (t < 128) {
        float v = dec(__ldcg(&g_amax[t * 32]));
        if (t < 64) hm[t] = v;
        else        ST[t - 64] = v + biasS[t - 64];
    }
    __syncthreads();                // hm/ST ready; this block's reads retired

    if (t == 0) lastRead = (atomicAdd(&g_cnt2, 1) == NB - 1);

    {   // features: one slot per thread (8 rows x 64 d) — pure smem math
        int frow = t >> 6, fd = t & 63;
        float av = (fd < D32) ? sa[frow][fd] : sc[frow][fd - D32];
        fS[frow * 64 + fd] = fmaxf(ST[fd] - av, 0.f);
    }
    // local K-fold: 16 FMAs per thread from registers
    {
        float kacc = 0.f;
        #pragma unroll
        for (int j = 0; j < 16; j++)
            kacc = fmaf(hm[g4 * 16 + j], w2[j], kacc);
        kp[g4 * 128 + o] = kacc;
    }
    __syncthreads();

    // last reader zeroes slots + resets flags for the next graph replay
    if (lastRead) {
        if (t < 128) g_amax[t * 32] = 0u;
        if (t == 0) { g_cnt2 = 0; g_flag = 0; }
    }

    // ========== phase C: GEMM from registers x smem features ==========
    {
        float acc[4] = {0.f, 0.f, 0.f, 0.f};
        #pragma unroll
        for (int j = 0; j < 32; j++) {
            #pragma unroll
            for (int r = 0; r < 4; r++)
                acc[r] = fmaf(fS[(rh * 4 + r) * 64 + ch * 32 + j], w[j], acc[r]);
        }
        #pragma unroll
        for (int r = 0; r < 4; r++)
            part[(g4 * 4 + r) * 128 + o] = acc[r];
    }
    __syncthreads();

    {   // combine d-halves + K + bias, write out: 1024 outputs, 2 per thread
        #pragma unroll
        for (int s = 0; s < 2; s++) {
            int slot = t + 512 * s;
            int row = slot >> 7, oo2 = slot & 127;
            int rh2 = row >> 2, r = row & 3;
            float K = biasS[64 + oo2] + kp[oo2] + kp[128 + oo2]
                                      + kp[256 + oo2] + kp[384 + oo2];
            out[(row0 + row) * OUTD + oo2] =
                K + part[((rh2 * 2) * 4 + r) * 128 + oo2]
                  + part[((rh2 * 2 + 1) * 4 + r) * 128 + oo2];
        }
    }
}

extern "C" void kernel_launch(void* const* d_in, const int* in_sizes, int n_in,
                              void* d_out, int out_size)
{
    const float* hs    = (const float*)d_in[0];
    const float* obs1  = (const float*)d_in[1];
    const float* obs   = (const float*)d_in[2];
    const float* W_sp  = (const float*)d_in[3];
    const float* b_sp  = (const float*)d_in[4];
    const float* W_vel = (const float*)d_in[5];
    const float* b_vel = (const float*)d_in[6];
    const float* W_hid = (const float*)d_in[7];
    const float* b_hid = (const float*)d_in[8];
    const float* W_out = (const float*)d_in[9];
    const float* b_out = (const float*)d_in[10];
    float* out = (float*)d_out;

    kf<<<NB, 512>>>(hs, obs1, obs, W_sp, b_sp, W_vel, b_vel,
                    W_hid, b_hid, W_out, b_out, out);
}

// round 16
// speedup vs baseline: 1.2636x; 1.1364x over previous
#include <cuda_runtime.h>

#define HID  128
#define MH   64
#define D32  32
#define OUTD 128
#define NB   128   // grid; 8 rows per block; <= SM count (co-resident)

// ---- device globals (no allocation allowed) ----
// 128 max-slots, each padded to its own 128B line (32 uints) to spread L2 slices.
// [0:64)=hid, [64:96)=a(spatial), [96:128)=c(vel). 0 = sentinel (< enc(any finite)).
__device__ unsigned     g_amax[128 * 32];
__device__ int          g_cnt;    // phase-A ticket (last setter resets)
__device__ int          g_cnt2;   // post-read ticket (last reader resets + zeroes)
__device__ volatile int g_flag;

// order-preserving float <-> uint encoding (unsigned compare == float compare)
__device__ __forceinline__ unsigned enc(float f) {
    unsigned u = __float_as_uint(f);
    return (u & 0x80000000u) ? ~u : (u | 0x80000000u);
}
__device__ __forceinline__ float dec(unsigned e) {
    return (e & 0x80000000u) ? __uint_as_float(e & 0x7FFFFFFFu)
                             : __uint_as_float(~e);
}

__global__ void __launch_bounds__(512) kf(
    const float* __restrict__ hs,
    const float* __restrict__ obs1,
    const float* __restrict__ obs,
    const float* __restrict__ W_sp,
    const float* __restrict__ b_sp,
    const float* __restrict__ W_vel,
    const float* __restrict__ b_vel,
    const float* __restrict__ W_hid,
    const float* __restrict__ b_hid,
    const float* __restrict__ W_out,
    const float* __restrict__ b_out,
    float* __restrict__ out)
{
    __shared__ float wS[HID][MH];   // 32 KB; phase-B/C scratch aliases here
    __shared__ float hsS[8][HID];   // 4 KB
    __shared__ float bhS[MH];       // 256 B
    __shared__ float biasS[192];    // [0:32) b_sp, [32:64) b_vel, [64:192) b_out
    __shared__ float sa[8][D32];    // 1 KB (live into phase C)
    __shared__ float sc[8][D32];    // 1 KB (live into phase C)
    __shared__ float p0[8][MH];     // 2 KB
    __shared__ float p1[8][MH];     // 2 KB
    __shared__ float red[4][MH];    // 1 KB
    __shared__ int   lastRead;

    int b = blockIdx.x, t = threadIdx.x;
    int row0 = b * 8;

    // phase-C roles: o(128) x g4(4); ch = d-half, rh = row-quad
    int o = t & 127, g4 = t >> 7;
    int ch = g4 & 1, rh = g4 >> 1;

    // ========== phase A staging: ALL loads independent, one wave ==========
    float w[32];                    // W_out[ch*32 + j][o]   (phase-C GEMM)
    float w2[16];                   // W_out[64 + g4*16 + j][o]  (local K-fold)
    {
        const float* wp = W_out + ch * 32 * OUTD + o;
        #pragma unroll
        for (int j = 0; j < 32; j++) w[j] = __ldg(&wp[j * OUTD]);
        const float* wp2 = W_out + (64 + g4 * 16) * OUTD + o;
        #pragma unroll
        for (int j = 0; j < 16; j++) w2[j] = __ldg(&wp2[j * OUTD]);
    }

    #pragma unroll
    for (int j = 0; j < 4; j++)     // W_hid: 2048 float4
        ((float4*)wS)[t + 512 * j] = ((const float4*)W_hid)[t + 512 * j];

    if (t < 64) bhS[t] = b_hid[t];
    if (t >= 64 && t < 256) {       // biases (independent)
        int x = t - 64;
        if (x < 192)
            biasS[x] = (x < 32) ? b_sp[x] : (x < 64) ? b_vel[x - 32]
                                                     : b_out[x - 64];
    }

    if (t < 256) {
        ((float4*)hsS)[t] = ((const float4*)(hs + row0 * HID))[t];
    } else {
        int tt = t - 256;
        int row = tt >> 5, d = tt & 31;
        int i = row0 + row;
        float2 oo = ((const float2*)obs)[i];
        float2 o1 = ((const float2*)obs1)[i];
        sa[row][d] = fmaf(oo.x, W_sp[d], oo.y * W_sp[D32 + d]);
        float vx = 4.f * (oo.x - o1.x), vy = 4.f * (oo.y - o1.y);
        sc[row][d] = fmaf(vx, W_vel[d], vy * W_vel[D32 + d]);
    }
    __syncthreads();

    {   // hidden GEMM from smem: k(64) x ch2(2 c-halves) x rg(4 row-pairs)
        // h reads vectorized to float4: 192 -> 96 warp-LDS per warp
        int k = t & 63, g = t >> 6;
        int ch2 = g & 1, rg = g >> 1;
        const float* wp = &wS[ch2 * 64][k];
        const float4* h0 = (const float4*)&hsS[rg * 2][ch2 * 64];
        const float4* h1 = (const float4*)&hsS[rg * 2 + 1][ch2 * 64];
        float a0 = 0.f, a1 = 0.f;
        #pragma unroll
        for (int c4 = 0; c4 < 16; c4++) {
            float4 x0 = h0[c4];
            float4 x1 = h1[c4];
            float w0 = wp[(c4 * 4 + 0) * MH];
            float w1 = wp[(c4 * 4 + 1) * MH];
            float wv2 = wp[(c4 * 4 + 2) * MH];
            float w3 = wp[(c4 * 4 + 3) * MH];
            a0 = fmaf(x0.x, w0, a0); a1 = fmaf(x1.x, w0, a1);
            a0 = fmaf(x0.y, w1, a0); a1 = fmaf(x1.y, w1, a1);
            a0 = fmaf(x0.z, wv2, a0); a1 = fmaf(x1.z, wv2, a1);
            a0 = fmaf(x0.w, w3, a0); a1 = fmaf(x1.w, w3, a1);
        }
        p0[g][k] = a0;
        p1[g][k] = a1;
    }
    __syncthreads();

    if (t < 256) {                  // combine c-halves, relu, max over 2 rows
        int k = t & 63, rg = t >> 6;
        float bk = bhS[k];
        float a0 = bk + p0[rg * 2][k] + p0[rg * 2 + 1][k];
        float a1 = bk + p1[rg * 2][k] + p1[rg * 2 + 1][k];
        red[rg][k] = fmaxf(fmaxf(a0, a1), 0.f);
    }
    __syncthreads();

    // per-block maxes -> padded global atomicMax slots (spread across L2 slices)
    if (t < 64) {
        float m = fmaxf(fmaxf(red[0][t], red[1][t]),
                        fmaxf(red[2][t], red[3][t]));
        atomicMax(&g_amax[t * 32], enc(m));
    } else if (t < 96) {
        int d = t - 64;
        float m = sa[0][d];
        #pragma unroll
        for (int r = 1; r < 8; r++) m = fmaxf(m, sa[r][d]);
        atomicMax(&g_amax[t * 32], enc(m));
    } else if (t < 128) {
        int d = t - 96;
        float m = sc[0][d];
        #pragma unroll
        for (int r = 1; r < 8; r++) m = fmaxf(m, sc[r][d]);
        atomicMax(&g_amax[t * 32], enc(m));
    }
    __syncthreads();                // all atomics issued before the ticket
    __threadfence();
    if (t == 0) {
        if (atomicAdd(&g_cnt, 1) == NB - 1) {
            g_cnt = 0;              // safe: provably last incrementer
            g_flag = 1;             // maxes are already final -> release
        }
        while (g_flag == 0) __nanosleep(64);
    }
    __syncthreads();

    // ========== phase B: read maxes (1 L2 wave), local K, features ==========
    float* hm = &wS[0][0];          // [64]   — aliases wS (weights done)
    float* ST = hm + 64;            // [64]: [0:32)=S, [32:64)=T
    float* fS = ST + 64;            // [8][64] = 512   (base 128 floats: 512B aligned)
    float* kp = fS + 512;           // [4][128] = 512
    float* part = kp + 512;         // [4][4][128] = 2048

    if (t < 128) {
        float v = dec(__ldcg(&g_amax[t * 32]));
        if (t < 64) hm[t] = v;
        else        ST[t - 64] = v + biasS[t - 64];
    }
    __syncthreads();                // hm/ST ready; this block's reads retired

    if (t == 0) lastRead = (atomicAdd(&g_cnt2, 1) == NB - 1);

    {   // features: one slot per thread (8 rows x 64 d) — pure smem math
        int frow = t >> 6, fd = t & 63;
        float av = (fd < D32) ? sa[frow][fd] : sc[frow][fd - D32];
        fS[frow * 64 + fd] = fmaxf(ST[fd] - av, 0.f);
    }
    // local K-fold: 16 FMAs per thread from registers (hm as float4 broadcast)
    {
        const float4* hm4 = (const float4*)&hm[g4 * 16];
        float kacc = 0.f;
        #pragma unroll
        for (int j4 = 0; j4 < 4; j4++) {
            float4 hv = hm4[j4];
            kacc = fmaf(hv.x, w2[j4 * 4 + 0], kacc);
            kacc = fmaf(hv.y, w2[j4 * 4 + 1], kacc);
            kacc = fmaf(hv.z, w2[j4 * 4 + 2], kacc);
            kacc = fmaf(hv.w, w2[j4 * 4 + 3], kacc);
        }
        kp[g4 * 128 + o] = kacc;
    }
    __syncthreads();

    // last reader zeroes slots + resets flags for the next graph replay
    if (lastRead) {
        if (t < 128) g_amax[t * 32] = 0u;
        if (t == 0) { g_cnt2 = 0; g_flag = 0; }
    }

    // ========== phase C: GEMM from registers x smem features (float4 f) ==========
    {
        float acc[4] = {0.f, 0.f, 0.f, 0.f};
        #pragma unroll
        for (int r = 0; r < 4; r++) {
            const float4* f4 = (const float4*)&fS[(rh * 4 + r) * 64 + ch * 32];
            #pragma unroll
            for (int j4 = 0; j4 < 8; j4++) {
                float4 fv = f4[j4];
                acc[r] = fmaf(fv.x, w[j4 * 4 + 0], acc[r]);
                acc[r] = fmaf(fv.y, w[j4 * 4 + 1], acc[r]);
                acc[r] = fmaf(fv.z, w[j4 * 4 + 2], acc[r]);
                acc[r] = fmaf(fv.w, w[j4 * 4 + 3], acc[r]);
            }
        }
        #pragma unroll
        for (int r = 0; r < 4; r++)
            part[(g4 * 4 + r) * 128 + o] = acc[r];
    }
    __syncthreads();

    {   // combine d-halves + K + bias, write out: 1024 outputs, 2 per thread
        #pragma unroll
        for (int s = 0; s < 2; s++) {
            int slot = t + 512 * s;
            int row = slot >> 7, oo2 = slot & 127;
            int rh2 = row >> 2, r = row & 3;
            float K = biasS[64 + oo2] + kp[oo2] + kp[128 + oo2]
                                      + kp[256 + oo2] + kp[384 + oo2];
            out[(row0 + row) * OUTD + oo2] =
                K + part[((rh2 * 2) * 4 + r) * 128 + oo2]
                  + part[((rh2 * 2 + 1) * 4 + r) * 128 + oo2];
        }
    }
}

extern "C" void kernel_launch(void* const* d_in, const int* in_sizes, int n_in,
                              void* d_out, int out_size)
{
    const float* hs    = (const float*)d_in[0];
    const float* obs1  = (const float*)d_in[1];
    const float* obs   = (const float*)d_in[2];
    const float* W_sp  = (const float*)d_in[3];
    const float* b_sp  = (const float*)d_in[4];
    const float* W_vel = (const float*)d_in[5];
    const float* b_vel = (const float*)d_in[6];
    const float* W_hid = (const float*)d_in[7];
    const float* b_hid = (const float*)d_in[8];
    const float* W_out = (const float*)d_in[9];
    const float* b_out = (const float*)d_in[10];
    float* out = (float*)d_out;

    kf<<<NB, 512>>>(hs, obs1, obs, W_sp, b_sp, W_vel, b_vel,
                    W_hid, b_hid, W_out, b_out, out);
}

// round 17
// speedup vs baseline: 1.2752x; 1.0092x over previous
#include <cuda_runtime.h>

#define HID  128
#define MH   64
#define D32  32
#define OUTD 128
#define NB   128   // grid; 8 rows per block; <= SM count (co-resident)

// ---- device globals (no allocation allowed) ----
// 128 max-slots, each padded to its own 128B line (32 uints) to spread L2 slices.
// [0:64)=hid, [64:96)=a(spatial), [96:128)=c(vel). 0 = sentinel (< enc(any finite)).
__device__ unsigned     g_amax[128 * 32];
__device__ int          g_cnt;    // phase-A ticket (last setter resets)
__device__ int          g_cnt2;   // post-read ticket (last reader resets + zeroes)
__device__ volatile int g_flag;

// order-preserving float <-> uint encoding (unsigned compare == float compare)
__device__ __forceinline__ unsigned enc(float f) {
    unsigned u = __float_as_uint(f);
    return (u & 0x80000000u) ? ~u : (u | 0x80000000u);
}
__device__ __forceinline__ float dec(unsigned e) {
    return (e & 0x80000000u) ? __uint_as_float(e & 0x7FFFFFFFu)
                             : __uint_as_float(~e);
}

__global__ void __launch_bounds__(512) kf(
    const float* __restrict__ hs,
    const float* __restrict__ obs1,
    const float* __restrict__ obs,
    const float* __restrict__ W_sp,
    const float* __restrict__ b_sp,
    const float* __restrict__ W_vel,
    const float* __restrict__ b_vel,
    const float* __restrict__ W_hid,
    const float* __restrict__ b_hid,
    const float* __restrict__ W_out,
    const float* __restrict__ b_out,
    float* __restrict__ out)
{
    __shared__ float wS[HID][MH];   // 32 KB; phase-B/C scratch aliases here
    __shared__ float hsS[8][HID];   // 4 KB
    __shared__ float bhS[MH];       // 256 B
    __shared__ float biasS[192];    // [0:32) b_sp, [32:64) b_vel, [64:192) b_out
    __shared__ float sa[8][D32];    // 1 KB (live into phase C)
    __shared__ float sc[8][D32];    // 1 KB (live into phase C)
    __shared__ float p[4][4][64];   // 4 KB  [g = rq*2+ch][r][k]
    __shared__ int   lastRead;

    int b = blockIdx.x, t = threadIdx.x;
    int row0 = b * 8;

    // weight-ownership role: o(128) x seg(4). seg 0/1 -> phase-C GEMM d-halves,
    // seg 2/3 -> K-fold k-halves. Zero duplication: 512 x 32 = 16384 = |W_out|.
    int o = t & 127, seg = t >> 7;

    // ========== phase A staging: ALL loads independent, one wave ==========
    float wreg[32];                 // W_out[seg*32 + j][o]
    {
        const float* wp = W_out + seg * 32 * OUTD + o;
        #pragma unroll
        for (int j = 0; j < 32; j++) wreg[j] = __ldg(&wp[j * OUTD]);
    }

    #pragma unroll
    for (int j = 0; j < 4; j++)     // W_hid: 2048 float4
        ((float4*)wS)[t + 512 * j] = ((const float4*)W_hid)[t + 512 * j];

    if (t < 64) bhS[t] = b_hid[t];
    if (t >= 64 && t < 256) {       // biases (independent)
        int x = t - 64;
        if (x < 192)
            biasS[x] = (x < 32) ? b_sp[x] : (x < 64) ? b_vel[x - 32]
                                                     : b_out[x - 64];
    }

    if (t < 256) {
        ((float4*)hsS)[t] = ((const float4*)(hs + row0 * HID))[t];
    } else {
        int tt = t - 256;
        int row = tt >> 5, d = tt & 31;
        int i = row0 + row;
        float2 oo = ((const float2*)obs)[i];
        float2 o1 = ((const float2*)obs1)[i];
        sa[row][d] = fmaf(oo.x, W_sp[d], oo.y * W_sp[D32 + d]);
        float vx = 4.f * (oo.x - o1.x), vy = 4.f * (oo.y - o1.y);
        sc[row][d] = fmaf(vx, W_vel[d], vy * W_vel[D32 + d]);
    }
    __syncthreads();

    // ---- sa/sc maxes + atomics: threads 448-511, OVERLAPS the GEMM below ----
    if (t >= 448) {
        int x = t - 448;            // 0..63: [0:32)=sa, [32:64)=sc
        float m;
        if (x < 32) {
            m = sa[0][x];
            #pragma unroll
            for (int r = 1; r < 8; r++) m = fmaxf(m, sa[r][x]);
            atomicMax(&g_amax[(64 + x) * 32], enc(m));
        } else {
            int d = x - 32;
            m = sc[0][d];
            #pragma unroll
            for (int r = 1; r < 8; r++) m = fmaxf(m, sc[r][d]);
            atomicMax(&g_amax[(96 + d) * 32], enc(m));
        }
    }

    // ---- hidden GEMM: 256 threads = k(64) x ch2(2) x rq(2), 4 rows each ----
    if (t < 256) {
        int k = t & 63, g = t >> 6;      // g = rq*2 + ch2
        int ch2 = g & 1, rq = g >> 1;
        const float* wp = &wS[ch2 * 64][k];  // lanes k consecutive: conflict-free
        float a[4] = {0.f, 0.f, 0.f, 0.f};
        #pragma unroll
        for (int c4 = 0; c4 < 16; c4++) {
            float w0 = wp[(c4 * 4 + 0) * MH];
            float w1 = wp[(c4 * 4 + 1) * MH];
            float w2v = wp[(c4 * 4 + 2) * MH];
            float w3 = wp[(c4 * 4 + 3) * MH];
            #pragma unroll
            for (int r = 0; r < 4; r++) {
                float4 x = *(const float4*)&hsS[rq * 4 + r][ch2 * 64 + c4 * 4];
                a[r] = fmaf(x.x, w0, a[r]);
                a[r] = fmaf(x.y, w1, a[r]);
                a[r] = fmaf(x.z, w2v, a[r]);
                a[r] = fmaf(x.w, w3, a[r]);
            }
        }
        #pragma unroll
        for (int r = 0; r < 4; r++) p[g][r][k] = a[r];
    }
    __syncthreads();

    // ---- merged combine + relu + row-max + atomic: t < 64 ----
    if (t < 64) {
        float bk = bhS[t];
        float m = 0.f;               // relu floor folded into max
        #pragma unroll
        for (int row = 0; row < 8; row++) {
            int rq = row >> 2, r = row & 3;
            float v = bk + p[rq * 2][r][t] + p[rq * 2 + 1][r][t];
            m = fmaxf(m, v);
        }
        atomicMax(&g_amax[t * 32], enc(m));
    }
    __syncthreads();                // all atomics issued before the ticket
    __threadfence();
    if (t == 0) {
        if (atomicAdd(&g_cnt, 1) == NB - 1) {
            g_cnt = 0;              // safe: provably last incrementer
            g_flag = 1;             // maxes are already final -> release
        }
        while (g_flag == 0) __nanosleep(64);
    }
    __syncthreads();

    // ========== phase B: read maxes (1 L2 wave), features, K-fold ==========
    float* hm   = &wS[0][0];        // [64]   — aliases wS (weights done)
    float* ST   = hm + 64;          // [64]: [0:32)=S, [32:64)=T
    float* fS   = ST + 64;          // [8][64] = 512  (16B-aligned base)
    float* kp   = fS + 512;         // [2][128] = 256
    float* part = kp + 256;         // [2][8][128] = 2048

    if (t < 128) {
        float v = dec(__ldcg(&g_amax[t * 32]));
        if (t < 64) hm[t] = v;
        else        ST[t - 64] = v + biasS[t - 64];
    }
    __syncthreads();                // hm/ST ready; this block's reads retired

    if (t == 0) lastRead = (atomicAdd(&g_cnt2, 1) == NB - 1);

    {   // features: one slot per thread (8 rows x 64 d) — pure smem math
        int frow = t >> 6, fd = t & 63;
        float av = (fd < D32) ? sa[frow][fd] : sc[frow][fd - D32];
        fS[frow * 64 + fd] = fmaxf(ST[fd] - av, 0.f);
    }
    if (t >= 256) {                 // K-fold: owners of W_out[64:], 32 FMAs
        int kg = seg - 2;           // 0 or 1
        const float4* hm4 = (const float4*)&hm[kg * 32];
        float kacc = 0.f;
        #pragma unroll
        for (int j4 = 0; j4 < 8; j4++) {
            float4 hv = hm4[j4];
            kacc = fmaf(hv.x, wreg[j4 * 4 + 0], kacc);
            kacc = fmaf(hv.y, wreg[j4 * 4 + 1], kacc);
            kacc = fmaf(hv.z, wreg[j4 * 4 + 2], kacc);
            kacc = fmaf(hv.w, wreg[j4 * 4 + 3], kacc);
        }
        kp[kg * 128 + o] = kacc;
    }
    __syncthreads();

    // last reader zeroes slots + resets flags for the next graph replay
    if (lastRead) {
        if (t < 128) g_amax[t * 32] = 0u;
        if (t == 0) { g_cnt2 = 0; g_flag = 0; }
    }

    // ========== phase C: GEMM — each (ch,o) owner computes all 8 rows ==========
    if (t < 256) {                  // seg = ch here (0 or 1)
        float acc[8];
        #pragma unroll
        for (int r = 0; r < 8; r++) acc[r] = 0.f;
        #pragma unroll
        for (int j4 = 0; j4 < 8; j4++) {
            float w0 = wreg[j4 * 4 + 0], w1 = wreg[j4 * 4 + 1];
            float w2v = wreg[j4 * 4 + 2], w3 = wreg[j4 * 4 + 3];
            #pragma unroll
            for (int r = 0; r < 8; r++) {
                float4 fv = *(const float4*)&fS[r * 64 + seg * 32 + j4 * 4];
                acc[r] = fmaf(fv.x, w0, acc[r]);
                acc[r] = fmaf(fv.y, w1, acc[r]);
                acc[r] = fmaf(fv.z, w2v, acc[r]);
                acc[r] = fmaf(fv.w, w3, acc[r]);
            }
        }
        #pragma unroll
        for (int r = 0; r < 8; r++)
            part[seg * 1024 + r * 128 + o] = acc[r];
    }
    __syncthreads();

    {   // combine d-halves + K + bias, write out: 1024 outputs, 2 per thread
        #pragma unroll
        for (int s = 0; s < 2; s++) {
            int slot = t + 512 * s;
            int row = slot >> 7, oo2 = slot & 127;
            float K = biasS[64 + oo2] + kp[oo2] + kp[128 + oo2];
            out[(row0 + row) * OUTD + oo2] =
                K + part[row * 128 + oo2] + part[1024 + row * 128 + oo2];
        }
    }
}

extern "C" void kernel_launch(void* const* d_in, const int* in_sizes, int n_in,
                              void* d_out, int out_size)
{
    const float* hs    = (const float*)d_in[0];
    const float* obs1  = (const float*)d_in[1];
    const float* obs   = (const float*)d_in[2];
    const float* W_sp  = (const float*)d_in[3];
    const float* b_sp  = (const float*)d_in[4];
    const float* W_vel = (const float*)d_in[5];
    const float* b_vel = (const float*)d_in[6];
    const float* W_hid = (const float*)d_in[7];
    const float* b_hid = (const float*)d_in[8];
    const float* W_out = (const float*)d_in[9];
    const float* b_out = (const float*)d_in[10];
    float* out = (float*)d_out;

    kf<<<NB, 512>>>(hs, obs1, obs, W_sp, b_sp, W_vel, b_vel,
                    W_hid, b_hid, W_out, b_out, out);
}